// round 16
// baseline (speedup 1.0000x reference)
#include <cuda_runtime.h>
#include <cuda_fp16.h>
#include <mma.h>
#include <cstdint>
#include <math.h>

using namespace nvcuda;

#define FULL 0xFFFFFFFFu
#define NMAX 50048
#define EMAX 1205248          // E + up to 7 pad per node
#define VSTRIDE ((size_t)NMAX * 128)
#define SCAN_FLAG 0x40000000
#define SCAN_MASK 0x3FFFFFFF

// dynamic smem layout for fat1 gemm role
#define DS_AS 0                    // __half As[128][136] = 34816 B
#define DS_BS 34816                // __half Bs[128][72]  = 18432 B
#define DS_ST (34816 + 18432)      // float stage[8][256] =  8192 B
#define DS_TOTAL 61440

// ---------------- device scratch (zero-init at load; final_kernel re-zeroes
// g_cnt/g_bsum each call; feat rows >= N stay zero forever -> dummy gather target) ----------------
__device__ __half g_feat[3][NMAX * 128];
__device__ float  g_el[3][NMAX * 8];
__device__ float  g_er[3][NMAX * 8];
__device__ float  g_views[3 * VSTRIDE];
__device__ int    g_cnt[3][NMAX];
__device__ int    g_rowoff[3][NMAX + 1];
__device__ int    g_cursor[3][NMAX];
__device__ int    g_csr[3][EMAX];
__device__ int    g_bsum[3 * 64];
__device__ double g_qk[3];
__device__ double g_dm[3];
__device__ float  g_coef[8];

// ---------------- helpers ----------------
__device__ __forceinline__ float wsum(float v) {
    v += __shfl_xor_sync(FULL, v, 16);
    v += __shfl_xor_sync(FULL, v, 8);
    v += __shfl_xor_sync(FULL, v, 4);
    v += __shfl_xor_sync(FULL, v, 2);
    v += __shfl_xor_sync(FULL, v, 1);
    return v;
}
__device__ __forceinline__ unsigned long long pk2(float lo, float hi) {
    unsigned long long r;
    asm("mov.b64 %0, {%1, %2};" : "=l"(r) : "f"(lo), "f"(hi));
    return r;
}
__device__ __forceinline__ void up2(unsigned long long v, float& lo, float& hi) {
    asm("mov.b64 {%0, %1}, %2;" : "=f"(lo), "=f"(hi) : "l"(v));
}
__device__ __forceinline__ void fma2(unsigned long long& d, unsigned long long a, unsigned long long b) {
    asm("fma.rn.f32x2 %0, %1, %2, %0;" : "+l"(d) : "l"(a), "l"(b));
}

// ---------------- fat1: interleaved GEMM (3 views, fused el/er) + count blocks ----------------
__global__ __launch_bounds__(256) void fat1_kernel(const float* __restrict__ x,
                                                   const float* __restrict__ W0,
                                                   const float* __restrict__ W1,
                                                   const float* __restrict__ W2,
                                                   const float* __restrict__ al0,
                                                   const float* __restrict__ al1,
                                                   const float* __restrict__ al2,
                                                   const float* __restrict__ ar0,
                                                   const float* __restrict__ ar1,
                                                   const float* __restrict__ ar2,
                                                   const int* __restrict__ d0,
                                                   const int* __restrict__ d1,
                                                   const int* __restrict__ d2,
                                                   int N, int E, int G, int C, int Q4) {
    extern __shared__ char dsm[];
    int tid = threadIdx.x;

    int bid = blockIdx.x;
    int M2 = 2 * ((G < C) ? G : C);
    bool isGemm;
    int role;
    if (bid < M2) { isGemm = ((bid & 1) == 0); role = bid >> 1; }
    else if (G < C) { isGemm = false; role = (bid - M2) + G; }
    else { isGemm = true; role = (bid - M2) + C; }

    if (!isGemm) {
        int t = role * 256 + tid;
        if (t >= 3 * Q4) return;
        int v = t / Q4, q = t - v * Q4;
        const int* dst = (v == 0) ? d0 : (v == 1) ? d1 : d2;
        int base = q * 4;
        if (base + 4 <= E) {
            int4 dd = *(const int4*)&dst[base];
            atomicAdd(&g_cnt[v][dd.x], 1);
            atomicAdd(&g_cnt[v][dd.y], 1);
            atomicAdd(&g_cnt[v][dd.z], 1);
            atomicAdd(&g_cnt[v][dd.w], 1);
        } else {
            for (int e = base; e < E; e++) atomicAdd(&g_cnt[v][dst[e]], 1);
        }
        return;
    }

    // ---- GEMM: one block per row-tile, loops over all 3 views ----
    __half* As = (__half*)(dsm + DS_AS);      // [128][136]
    __half* Bs = (__half*)(dsm + DS_BS);      // [128][72]
    float* stage = (float*)(dsm + DS_ST);     // [8][256]
    int rowBase = role * 128;
    int wid = tid >> 5, lane = tid & 31;
    int warpM = wid >> 2;
    int warpN = wid & 3;

#pragma unroll
    for (int q = tid; q < 4096; q += 256) {
        int r = q >> 5, c = (q & 31) * 4;
        float4 f = make_float4(0.f, 0.f, 0.f, 0.f);
        if (rowBase + r < N) f = *(const float4*)&x[(size_t)(rowBase + r) * 128 + c];
        As[r * 136 + c + 0] = __float2half_rn(f.x);
        As[r * 136 + c + 1] = __float2half_rn(f.y);
        As[r * 136 + c + 2] = __float2half_rn(f.z);
        As[r * 136 + c + 3] = __float2half_rn(f.w);
    }
    __syncthreads();

    for (int v = 0; v < 3; v++) {
        const float* W = (v == 0) ? W0 : (v == 1) ? W1 : W2;
        const float* al = (v == 0) ? al0 : (v == 1) ? al1 : al2;
        const float* ar = (v == 0) ? ar0 : (v == 1) ? ar1 : ar2;
        wmma::fragment<wmma::accumulator, 16, 16, 16, float> acc[4][2];
#pragma unroll
        for (int m = 0; m < 4; m++)
#pragma unroll
            for (int n = 0; n < 2; n++) wmma::fill_fragment(acc[m][n], 0.0f);

        for (int k0 = 0; k0 < 128; k0 += 64) {
#pragma unroll
            for (int q = tid; q < 2048; q += 256) {
                int r = q >> 4, c = (q & 15) * 4;
                float4 f = *(const float4*)&W[(size_t)r * 128 + k0 + c];
                Bs[r * 72 + c + 0] = __float2half_rn(f.x);
                Bs[r * 72 + c + 1] = __float2half_rn(f.y);
                Bs[r * 72 + c + 2] = __float2half_rn(f.z);
                Bs[r * 72 + c + 3] = __float2half_rn(f.w);
            }
            __syncthreads();
#pragma unroll
            for (int kk = 0; kk < 64; kk += 16) {
                wmma::fragment<wmma::matrix_a, 16, 16, 16, __half, wmma::row_major> a[4];
                wmma::fragment<wmma::matrix_b, 16, 16, 16, __half, wmma::col_major> b[2];
#pragma unroll
                for (int m = 0; m < 4; m++)
                    wmma::load_matrix_sync(a[m], &As[(warpM * 64 + m * 16) * 136 + k0 + kk], 136);
#pragma unroll
                for (int n = 0; n < 2; n++)
                    wmma::load_matrix_sync(b[n], &Bs[(warpN * 32 + n * 16) * 72 + kk], 72);
#pragma unroll
                for (int m = 0; m < 4; m++)
#pragma unroll
                    for (int n = 0; n < 2; n++)
                        wmma::mma_sync(acc[m][n], a[m], b[n], acc[m][n]);
            }
            __syncthreads();
        }

        // epilogue: feat write + fused el/er
#pragma unroll
        for (int m = 0; m < 4; m++)
#pragma unroll
            for (int n = 0; n < 2; n++) {
                wmma::store_matrix_sync(&stage[wid * 256], acc[m][n], 16, wmma::mem_row_major);
                __syncwarp();
                int r = lane >> 1, c0 = (lane & 1) * 8;
                int grow = rowBase + warpM * 64 + m * 16 + r;
                int head = 2 * warpN + n;
                const float* sp = &stage[wid * 256 + r * 16 + c0];
                float elp = 0.f, erp = 0.f;
#pragma unroll
                for (int j = 0; j < 8; j++) {
                    float fv = sp[j];
                    elp += fv * al[head * 16 + c0 + j];
                    erp += fv * ar[head * 16 + c0 + j];
                }
                elp += __shfl_xor_sync(FULL, elp, 1);
                erp += __shfl_xor_sync(FULL, erp, 1);
                if (grow < N) {
                    __half h[8];
#pragma unroll
                    for (int j = 0; j < 8; j++) h[j] = __float2half_rn(sp[j]);
                    *(uint4*)&g_feat[v][(size_t)grow * 128 + warpN * 32 + n * 16 + c0] = *(uint4*)h;
                    if ((lane & 1) == 0) {
                        g_el[v][grow * 8 + head] = elp;
                        g_er[v][grow * 8 + head] = erp;
                    }
                }
                __syncwarp();
            }
    }
}

// ---------------- single-pass decoupled-lookback scan over PADDED counts ----------------
__global__ void scanDL_kernel(int N, int BV, int E) {
    int v = blockIdx.x / BV, b = blockIdx.x % BV;
    int tid = threadIdx.x;
    int lane = tid & 31, w = tid >> 5;
    if (blockIdx.x == 0 && tid < 3) { g_qk[tid] = 0.0; g_dm[tid] = 0.0; }
    if (b == 0 && tid < 8) g_el[v][N * 8 + tid] = -1e30f;   // dummy sentinel
    int i = b * 1024 + tid;
    int raw = (i < N) ? g_cnt[v][i] : 0;
    int val = (raw + 7) & ~7;        // padded
    __shared__ int ws[32];
    __shared__ int carry_s;

    int s = val;
#pragma unroll
    for (int o = 16; o >= 1; o >>= 1) s += __shfl_xor_sync(FULL, s, o);
    if (lane == 0) ws[w] = s;
    __syncthreads();
    if (w == 0) {
        int t = ws[lane];
#pragma unroll
        for (int o = 16; o >= 1; o >>= 1) t += __shfl_xor_sync(FULL, t, o);
        if (lane == 0) atomicExch(&g_bsum[v * BV + b], t | SCAN_FLAG);
    }
    if (w == 1) {
        volatile int* bs = (volatile int*)&g_bsum[v * BV];
        int a0 = 0, a1 = 0;
        if (lane < b) { do { a0 = bs[lane]; } while ((a0 & SCAN_FLAG) == 0); }
        if (lane + 32 < b) { do { a1 = bs[lane + 32]; } while ((a1 & SCAN_FLAG) == 0); }
        int t = ((lane < b) ? (a0 & SCAN_MASK) : 0) + ((lane + 32 < b) ? (a1 & SCAN_MASK) : 0);
#pragma unroll
        for (int o = 16; o >= 1; o >>= 1) t += __shfl_xor_sync(FULL, t, o);
        if (lane == 0) carry_s = t;
    }
    int x = val;
#pragma unroll
    for (int o = 1; o < 32; o <<= 1) {
        int t = __shfl_up_sync(FULL, x, o);
        if (lane >= o) x += t;
    }
    if (lane == 31) ws[w] = x;
    __syncthreads();
    if (w == 0) {
        int t = ws[lane];
        int y = t;
#pragma unroll
        for (int o = 1; o < 32; o <<= 1) {
            int u = __shfl_up_sync(FULL, y, o);
            if (lane >= o) y += u;
        }
        ws[lane] = y - t;
    }
    __syncthreads();
    int excl = x - val + ws[w] + carry_s;
    if (i < N) {
        g_rowoff[v][i] = excl;
        g_cursor[v][i] = excl;
        for (int k = raw; k < val; k++) g_csr[v][excl + k] = N;
        if (i == N - 1) g_rowoff[v][N] = excl + val;
    }
}

// ---------------- fill (CSR scatter of real edges) ----------------
__global__ void fill_kernel(const int* __restrict__ s0, const int* __restrict__ s1,
                            const int* __restrict__ s2,
                            const int* __restrict__ d0, const int* __restrict__ d1,
                            const int* __restrict__ d2, int E, int Q4) {
    int t = blockIdx.x * blockDim.x + threadIdx.x;
    if (t >= 3 * Q4) return;
    int v = t / Q4, q = t - v * Q4;
    const int* src = (v == 0) ? s0 : (v == 1) ? s1 : s2;
    const int* dst = (v == 0) ? d0 : (v == 1) ? d1 : d2;
    int base = q * 4;
    if (base + 4 <= E) {
        int4 ss = *(const int4*)&src[base];
        int4 dd = *(const int4*)&dst[base];
        g_csr[v][atomicAdd(&g_cursor[v][dd.x], 1)] = ss.x;
        g_csr[v][atomicAdd(&g_cursor[v][dd.y], 1)] = ss.y;
        g_csr[v][atomicAdd(&g_cursor[v][dd.z], 1)] = ss.z;
        g_csr[v][atomicAdd(&g_cursor[v][dd.w], 1)] = ss.w;
    } else {
        for (int e = base; e < E; e++)
            g_csr[v][atomicAdd(&g_cursor[v][dst[e]], 1)] = src[e];
    }
}

// ---------------- attention + fused view reductions (low-reg tail, 5 blocks/SM) ----------------
__global__ __launch_bounds__(256, 5) void attn_kernel(const float* __restrict__ Wq,
                                                      const float* __restrict__ bq,
                                                      const float* __restrict__ Wk,
                                                      const float* __restrict__ bk,
                                                      const float* __restrict__ Wm,
                                                      const float* __restrict__ b0,
                                                      const float* __restrict__ b1,
                                                      const float* __restrict__ b2,
                                                      int N, int totalWarps) {
    __shared__ float sWqP[2048];
    __shared__ float sWkP[2048];
    __shared__ float sqk[3], sdm[3];
    int tid = threadIdx.x;
    for (int i = tid; i < 2048; i += 256) {
        int h = i >> 7, j = i & 127;
        int u = (h >> 1) * 128 + (j & 3) * 32 + (j >> 2);
        sWqP[u * 2 + (h & 1)] = Wq[i];
        sWkP[u * 2 + (h & 1)] = Wk[i];
    }
    if (tid < 3) { sqk[tid] = 0.f; sdm[tid] = 0.f; }
    __syncthreads();
    const unsigned long long* q8 = (const unsigned long long*)sWqP;
    const unsigned long long* k8 = (const unsigned long long*)sWkP;
    int l = tid & 31;
    int h1 = l & 7;
    int h2 = l >> 2;
    float bqv = bq[l & 15], bkv = bk[l & 15];
    int gw = (blockIdx.x * 256 + tid) >> 5;

    for (int idx = gw; idx < 3 * N; idx += totalWarps) {
        int v = idx / N;
        int d = idx - v * N;
        int off = g_rowoff[v][d];
        int nE = g_rowoff[v][d + 1] - off;    // multiple of 8
        const int* csr = &g_csr[v][off];
        const float* elv = g_el[v];
        const __half* featv = g_feat[v];
        const float* bvp = (v == 0) ? b0 : (v == 1) ? b1 : b2;
        float er1 = g_er[v][d * 8 + h1];

        float acc0 = 0.f, acc1 = 0.f, acc2 = 0.f, acc3 = 0.f, ssum = 0.f;
        for (int base = 0; base < nE; base += 8) {
            int j0 = base + (l >> 3);
            int s0 = csr[j0];
            int s1 = csr[j0 + 4];
            float e0 = elv[s0 * 8 + h1] + er1;
            float e1 = elv[s1 * 8 + h1] + er1;
            float p0 = __expf(fmaxf(e0, 0.2f * e0));
            float p1 = __expf(fmaxf(e1, 0.2f * e1));
            ssum += p0 + p1;
            int sk[8];
#pragma unroll
            for (int k = 0; k < 4; k++) {
                sk[k] = __shfl_sync(FULL, s0, k * 8);
                sk[4 + k] = __shfl_sync(FULL, s1, k * 8);
            }
            uint2 f[8];
#pragma unroll
            for (int k = 0; k < 8; k++)
                f[k] = *(const uint2*)&featv[(size_t)sk[k] * 128 + l * 4];
#pragma unroll
            for (int k = 0; k < 8; k++) {
                float ak = __shfl_sync(FULL, (k < 4) ? p0 : p1, (k & 3) * 8 + h2);
                float2 a = __half22float2(*(__half2*)&f[k].x);
                float2 b2v = __half22float2(*(__half2*)&f[k].y);
                acc0 += ak * a.x;
                acc1 += ak * a.y;
                acc2 += ak * b2v.x;
                acc3 += ak * b2v.y;
            }
        }
        ssum += __shfl_xor_sync(FULL, ssum, 8);
        ssum += __shfl_xor_sync(FULL, ssum, 16);
        float sinv = 1.0f / __shfl_sync(FULL, ssum, h2);
        float4 bb = *(const float4*)&bvp[l * 4];
        float4 o;
        o.x = fmaxf(acc0 * sinv + bb.x, 0.f);
        o.y = fmaxf(acc1 * sinv + bb.y, 0.f);
        o.z = fmaxf(acc2 * sinv + bb.z, 0.f);
        o.w = fmaxf(acc3 * sinv + bb.w, 0.f);
        *(float4*)&g_views[(size_t)v * VSTRIDE + (size_t)d * 128 + l * 4] = o;

        // ---- fused reductions (sequential q then k through ONE u64 array: lower reg peak) ----
        float4 wm = *(const float4*)&Wm[(size_t)d * 128 + l * 4];
        float dm = o.x * wm.x + o.y * wm.y + o.z * wm.z + o.w * wm.w;
        dm = wsum(dm);

        unsigned long long vp[4];
        vp[0] = pk2(o.x, o.x); vp[1] = pk2(o.y, o.y);
        vp[2] = pk2(o.z, o.z); vp[3] = pk2(o.w, o.w);
        float c[32];
        unsigned long long ac[8];
#pragma unroll
        for (int p = 0; p < 8; p++) ac[p] = 0ull;
#pragma unroll
        for (int p = 0; p < 8; p++)
#pragma unroll
            for (int jj = 0; jj < 4; jj++)
                fma2(ac[p], vp[jj], q8[p * 128 + jj * 32 + l]);
#pragma unroll
        for (int p = 0; p < 8; p++) up2(ac[p], c[2 * p], c[2 * p + 1]);
#pragma unroll
        for (int p = 0; p < 8; p++) ac[p] = 0ull;
#pragma unroll
        for (int p = 0; p < 8; p++)
#pragma unroll
            for (int jj = 0; jj < 4; jj++)
                fma2(ac[p], vp[jj], k8[p * 128 + jj * 32 + l]);
#pragma unroll
        for (int p = 0; p < 8; p++) up2(ac[p], c[16 + 2 * p], c[16 + 2 * p + 1]);
#pragma unroll
        for (int s = 16; s >= 1; s >>= 1) {
            bool hi = (l & s) != 0;
#pragma unroll
            for (int j = 0; j < s; j++) {
                float give = hi ? c[j] : c[j + s];
                float get = __shfl_xor_sync(FULL, give, s);
                c[j] = (hi ? c[j + s] : c[j]) + get;
            }
        }
        float other = __shfl_xor_sync(FULL, c[0], 16);
        float q = (l < 16) ? c[0] : other;
        float k = (l < 16) ? other : c[0];
        float qk = wsum((q + bqv) * (k + bkv)) * 0.5f;
        if (l == 0) {
            atomicAdd(&sqk[v], qk);
            atomicAdd(&sdm[v], dm);
        }
    }
    __syncthreads();
    if (tid < 3) {
        atomicAdd(&g_qk[tid], (double)sqk[tid]);
        atomicAdd(&g_dm[tid], (double)sdm[tid]);
    }
}

// ---------------- scalar fusion coefficients ----------------
__global__ void coef_kernel(const float* __restrict__ bm, int N) {
    if (threadIdx.x != 0 || blockIdx.x != 0) return;
    double inv = 1.0 / sqrt(16.0 * (double)N);
    double L[3] = {g_qk[0] * inv, g_qk[1] * inv, g_qk[2] * inv};
    double mx = fmax(L[0], fmax(L[1], L[2]));
    double e0 = exp(L[0] - mx), e1 = exp(L[1] - mx), e2 = exp(L[2] - mx);
    double se = e0 + e1 + e2;
    double wv[3] = {e0 / se, e1 / se, e2 / se};
#pragma unroll
    for (int v = 0; v < 3; v++) {
        double cv = 0.8 * wv[v] + 0.2;
        double om = 1.0 / (1.0 + exp(-(cv * g_dm[v] + (double)bm[0])));
        g_coef[v] = (float)(om * cv);
        g_coef[3 + v] = (float)(0.5 * cv);
    }
}

// ---------------- final elementwise (+ restore g_cnt/g_bsum for next call) ----------------
__global__ __launch_bounds__(256) void final_kernel(float* __restrict__ out, int N) {
    int gidx = blockIdx.x * 256 + threadIdx.x;
    if (gidx < 3 * NMAX) ((int*)g_cnt)[gidx] = 0;
    if (gidx < 192) g_bsum[gidx] = 0;
    size_t total = (size_t)N * 128;
    size_t i = (size_t)gidx * 4;
    if (i >= total) return;
    float a0 = g_coef[0], a1 = g_coef[1], a2 = g_coef[2];
    float r0 = g_coef[3], r1 = g_coef[4], r2 = g_coef[5];
    float4 s = *(const float4*)&g_views[i];
    float4 t = *(const float4*)&g_views[VSTRIDE + i];
    float4 p = *(const float4*)&g_views[2 * VSTRIDE + i];
    float4 mv;
    mv.x = a0 * s.x + a1 * t.x + a2 * p.x;
    mv.y = a0 * s.y + a1 * t.y + a2 * p.y;
    mv.z = a0 * s.z + a1 * t.z + a2 * p.z;
    mv.w = a0 * s.w + a1 * t.w + a2 * p.w;
    *(float4*)&out[i] = mv;
    float4 o;
    o.x = r0 * s.x + 0.5f * mv.x; o.y = r0 * s.y + 0.5f * mv.y;
    o.z = r0 * s.z + 0.5f * mv.z; o.w = r0 * s.w + 0.5f * mv.w;
    *(float4*)&out[total + i] = o;
    o.x = r1 * t.x + 0.5f * mv.x; o.y = r1 * t.y + 0.5f * mv.y;
    o.z = r1 * t.z + 0.5f * mv.z; o.w = r1 * t.w + 0.5f * mv.w;
    *(float4*)&out[2 * total + i] = o;
    o.x = r2 * p.x + 0.5f * mv.x; o.y = r2 * p.y + 0.5f * mv.y;
    o.z = r2 * p.z + 0.5f * mv.z; o.w = r2 * p.w + 0.5f * mv.w;
    *(float4*)&out[3 * total + i] = o;
}

// ---------------- launch ----------------
extern "C" void kernel_launch(void* const* d_in, const int* in_sizes, int n_in,
                              void* d_out, int out_size) {
    const float* x = (const float*)d_in[0];
    const int* s0 = (const int*)d_in[1], *d0 = (const int*)d_in[2];
    const int* s1 = (const int*)d_in[3], *d1 = (const int*)d_in[4];
    const int* s2 = (const int*)d_in[5], *d2 = (const int*)d_in[6];
    const float* W0 = (const float*)d_in[7],  *al0 = (const float*)d_in[8],
               * ar0 = (const float*)d_in[9],  *b0 = (const float*)d_in[10];
    const float* W1 = (const float*)d_in[11], *al1 = (const float*)d_in[12],
               * ar1 = (const float*)d_in[13], *b1 = (const float*)d_in[14];
    const float* W2 = (const float*)d_in[15], *al2 = (const float*)d_in[16],
               * ar2 = (const float*)d_in[17], *b2 = (const float*)d_in[18];
    const float* Wq = (const float*)d_in[19];
    const float* bq = (const float*)d_in[20];
    const float* Wk = (const float*)d_in[21];
    const float* bk = (const float*)d_in[22];
    const float* Wm = (const float*)d_in[23];
    const float* bm = (const float*)d_in[24];
    float* out = (float*)d_out;

    int N = in_sizes[0] / 128;
    int E = in_sizes[1];
    int BV = (N + 1023) >> 10;
    int NT = (N + 127) >> 7;
    int Q4 = (E + 3) >> 2;
    int gemmBlocks = NT;
    int edgeBlocks = (3 * Q4 + 255) / 256;
    int attnBlocks = 1480;

    static int smem_set = 0;
    if (!smem_set) {
        cudaFuncSetAttribute(fat1_kernel, cudaFuncAttributeMaxDynamicSharedMemorySize, DS_TOTAL);
        smem_set = 1;
    }

    fat1_kernel<<<gemmBlocks + edgeBlocks, 256, DS_TOTAL>>>(x, W0, W1, W2,
                                                            al0, al1, al2, ar0, ar1, ar2,
                                                            d0, d1, d2,
                                                            N, E, gemmBlocks, edgeBlocks, Q4);
    scanDL_kernel<<<3 * BV, 1024>>>(N, BV, E);
    fill_kernel<<<edgeBlocks, 256>>>(s0, s1, s2, d0, d1, d2, E, Q4);
    attn_kernel<<<attnBlocks, 256>>>(Wq, bq, Wk, bk, Wm, b0, b1, b2, N, attnBlocks * 8);
    coef_kernel<<<1, 32>>>(bm, N);
    final_kernel<<<((N * 32) + 255) / 256, 256>>>(out, N);
}

// round 17
// speedup vs baseline: 1.0401x; 1.0401x over previous
#include <cuda_runtime.h>
#include <cuda_fp16.h>
#include <mma.h>
#include <cstdint>
#include <math.h>

using namespace nvcuda;

#define FULL 0xFFFFFFFFu
#define NMAX 50048
#define EMAX 1205248          // E + up to 3 pad per node
#define VSTRIDE ((size_t)NMAX * 128)
#define SCAN_FLAG 0x40000000
#define SCAN_MASK 0x3FFFFFFF

// dynamic smem layout for fat1 gemm role
#define DS_AS 0                    // __half As[128][136] = 34816 B
#define DS_BS 34816                // __half Bs[128][72]  = 18432 B
#define DS_ST (34816 + 18432)      // float stage[8][256] =  8192 B
#define DS_TOTAL 61440

// ---------------- device scratch (zero-init at load; final_kernel re-zeroes
// g_cnt/g_bsum each call; feat rows >= N stay zero forever -> dummy gather target) ----------------
__device__ __half g_feat[3][NMAX * 128];
__device__ float  g_el[3][NMAX * 8];
__device__ float  g_er[3][NMAX * 8];
__device__ float  g_views[3 * VSTRIDE];
__device__ int    g_cnt[3][NMAX];
__device__ int    g_rowoff[3][NMAX + 1];
__device__ int    g_cursor[3][NMAX];
__device__ int    g_csr[3][EMAX];
__device__ int    g_bsum[3 * 64];
__device__ double g_qk[3];
__device__ double g_dm[3];
__device__ float  g_coef[8];

// ---------------- helpers ----------------
__device__ __forceinline__ float wsum(float v) {
    v += __shfl_xor_sync(FULL, v, 16);
    v += __shfl_xor_sync(FULL, v, 8);
    v += __shfl_xor_sync(FULL, v, 4);
    v += __shfl_xor_sync(FULL, v, 2);
    v += __shfl_xor_sync(FULL, v, 1);
    return v;
}
__device__ __forceinline__ unsigned long long pk2(float lo, float hi) {
    unsigned long long r;
    asm("mov.b64 %0, {%1, %2};" : "=l"(r) : "f"(lo), "f"(hi));
    return r;
}
__device__ __forceinline__ void up2(unsigned long long v, float& lo, float& hi) {
    asm("mov.b64 {%0, %1}, %2;" : "=f"(lo), "=f"(hi) : "l"(v));
}
__device__ __forceinline__ void fma2(unsigned long long& d, unsigned long long a, unsigned long long b) {
    asm("fma.rn.f32x2 %0, %1, %2, %0;" : "+l"(d) : "l"(a), "l"(b));
}

// ---------------- fat1: interleaved GEMM (3 views, fused el/er) + count blocks ----------------
__global__ __launch_bounds__(256) void fat1_kernel(const float* __restrict__ x,
                                                   const float* __restrict__ W0,
                                                   const float* __restrict__ W1,
                                                   const float* __restrict__ W2,
                                                   const float* __restrict__ al0,
                                                   const float* __restrict__ al1,
                                                   const float* __restrict__ al2,
                                                   const float* __restrict__ ar0,
                                                   const float* __restrict__ ar1,
                                                   const float* __restrict__ ar2,
                                                   const int* __restrict__ d0,
                                                   const int* __restrict__ d1,
                                                   const int* __restrict__ d2,
                                                   int N, int E, int G, int C, int Q4) {
    extern __shared__ char dsm[];
    int tid = threadIdx.x;

    int bid = blockIdx.x;
    int M2 = 2 * ((G < C) ? G : C);
    bool isGemm;
    int role;
    if (bid < M2) { isGemm = ((bid & 1) == 0); role = bid >> 1; }
    else if (G < C) { isGemm = false; role = (bid - M2) + G; }
    else { isGemm = true; role = (bid - M2) + C; }

    if (!isGemm) {
        int t = role * 256 + tid;
        if (t >= 3 * Q4) return;
        int v = t / Q4, q = t - v * Q4;
        const int* dst = (v == 0) ? d0 : (v == 1) ? d1 : d2;
        int base = q * 4;
        if (base + 4 <= E) {
            int4 dd = *(const int4*)&dst[base];
            atomicAdd(&g_cnt[v][dd.x], 1);
            atomicAdd(&g_cnt[v][dd.y], 1);
            atomicAdd(&g_cnt[v][dd.z], 1);
            atomicAdd(&g_cnt[v][dd.w], 1);
        } else {
            for (int e = base; e < E; e++) atomicAdd(&g_cnt[v][dst[e]], 1);
        }
        return;
    }

    // ---- GEMM: one block per row-tile, loops over all 3 views ----
    __half* As = (__half*)(dsm + DS_AS);      // [128][136]
    __half* Bs = (__half*)(dsm + DS_BS);      // [128][72]
    float* stage = (float*)(dsm + DS_ST);     // [8][256]
    int rowBase = role * 128;
    int wid = tid >> 5, lane = tid & 31;
    int warpM = wid >> 2;
    int warpN = wid & 3;

#pragma unroll
    for (int q = tid; q < 4096; q += 256) {
        int r = q >> 5, c = (q & 31) * 4;
        float4 f = make_float4(0.f, 0.f, 0.f, 0.f);
        if (rowBase + r < N) f = *(const float4*)&x[(size_t)(rowBase + r) * 128 + c];
        As[r * 136 + c + 0] = __float2half_rn(f.x);
        As[r * 136 + c + 1] = __float2half_rn(f.y);
        As[r * 136 + c + 2] = __float2half_rn(f.z);
        As[r * 136 + c + 3] = __float2half_rn(f.w);
    }
    __syncthreads();

    for (int v = 0; v < 3; v++) {
        const float* W = (v == 0) ? W0 : (v == 1) ? W1 : W2;
        const float* al = (v == 0) ? al0 : (v == 1) ? al1 : al2;
        const float* ar = (v == 0) ? ar0 : (v == 1) ? ar1 : ar2;
        wmma::fragment<wmma::accumulator, 16, 16, 16, float> acc[4][2];
#pragma unroll
        for (int m = 0; m < 4; m++)
#pragma unroll
            for (int n = 0; n < 2; n++) wmma::fill_fragment(acc[m][n], 0.0f);

        for (int k0 = 0; k0 < 128; k0 += 64) {
#pragma unroll
            for (int q = tid; q < 2048; q += 256) {
                int r = q >> 4, c = (q & 15) * 4;
                float4 f = *(const float4*)&W[(size_t)r * 128 + k0 + c];
                Bs[r * 72 + c + 0] = __float2half_rn(f.x);
                Bs[r * 72 + c + 1] = __float2half_rn(f.y);
                Bs[r * 72 + c + 2] = __float2half_rn(f.z);
                Bs[r * 72 + c + 3] = __float2half_rn(f.w);
            }
            __syncthreads();
#pragma unroll
            for (int kk = 0; kk < 64; kk += 16) {
                wmma::fragment<wmma::matrix_a, 16, 16, 16, __half, wmma::row_major> a[4];
                wmma::fragment<wmma::matrix_b, 16, 16, 16, __half, wmma::col_major> b[2];
#pragma unroll
                for (int m = 0; m < 4; m++)
                    wmma::load_matrix_sync(a[m], &As[(warpM * 64 + m * 16) * 136 + k0 + kk], 136);
#pragma unroll
                for (int n = 0; n < 2; n++)
                    wmma::load_matrix_sync(b[n], &Bs[(warpN * 32 + n * 16) * 72 + kk], 72);
#pragma unroll
                for (int m = 0; m < 4; m++)
#pragma unroll
                    for (int n = 0; n < 2; n++)
                        wmma::mma_sync(acc[m][n], a[m], b[n], acc[m][n]);
            }
            __syncthreads();
        }

        // epilogue: feat write + fused el/er
#pragma unroll
        for (int m = 0; m < 4; m++)
#pragma unroll
            for (int n = 0; n < 2; n++) {
                wmma::store_matrix_sync(&stage[wid * 256], acc[m][n], 16, wmma::mem_row_major);
                __syncwarp();
                int r = lane >> 1, c0 = (lane & 1) * 8;
                int grow = rowBase + warpM * 64 + m * 16 + r;
                int head = 2 * warpN + n;
                const float* sp = &stage[wid * 256 + r * 16 + c0];
                float elp = 0.f, erp = 0.f;
#pragma unroll
                for (int j = 0; j < 8; j++) {
                    float fv = sp[j];
                    elp += fv * al[head * 16 + c0 + j];
                    erp += fv * ar[head * 16 + c0 + j];
                }
                elp += __shfl_xor_sync(FULL, elp, 1);
                erp += __shfl_xor_sync(FULL, erp, 1);
                if (grow < N) {
                    __half h[8];
#pragma unroll
                    for (int j = 0; j < 8; j++) h[j] = __float2half_rn(sp[j]);
                    *(uint4*)&g_feat[v][(size_t)grow * 128 + warpN * 32 + n * 16 + c0] = *(uint4*)h;
                    if ((lane & 1) == 0) {
                        g_el[v][grow * 8 + head] = elp;
                        g_er[v][grow * 8 + head] = erp;
                    }
                }
                __syncwarp();
            }
    }
}

// ---------------- single-pass decoupled-lookback scan over counts padded to mult of 4 ----------------
__global__ void scanDL_kernel(int N, int BV, int E) {
    int v = blockIdx.x / BV, b = blockIdx.x % BV;
    int tid = threadIdx.x;
    int lane = tid & 31, w = tid >> 5;
    if (blockIdx.x == 0 && tid < 3) { g_qk[tid] = 0.0; g_dm[tid] = 0.0; }
    if (b == 0 && tid < 8) g_el[v][N * 8 + tid] = -1e30f;   // dummy sentinel
    int i = b * 1024 + tid;
    int raw = (i < N) ? g_cnt[v][i] : 0;
    int val = (raw + 3) & ~3;        // padded to multiple of 4
    __shared__ int ws[32];
    __shared__ int carry_s;

    int s = val;
#pragma unroll
    for (int o = 16; o >= 1; o >>= 1) s += __shfl_xor_sync(FULL, s, o);
    if (lane == 0) ws[w] = s;
    __syncthreads();
    if (w == 0) {
        int t = ws[lane];
#pragma unroll
        for (int o = 16; o >= 1; o >>= 1) t += __shfl_xor_sync(FULL, t, o);
        if (lane == 0) atomicExch(&g_bsum[v * BV + b], t | SCAN_FLAG);
    }
    if (w == 1) {
        volatile int* bs = (volatile int*)&g_bsum[v * BV];
        int a0 = 0, a1 = 0;
        if (lane < b) { do { a0 = bs[lane]; } while ((a0 & SCAN_FLAG) == 0); }
        if (lane + 32 < b) { do { a1 = bs[lane + 32]; } while ((a1 & SCAN_FLAG) == 0); }
        int t = ((lane < b) ? (a0 & SCAN_MASK) : 0) + ((lane + 32 < b) ? (a1 & SCAN_MASK) : 0);
#pragma unroll
        for (int o = 16; o >= 1; o >>= 1) t += __shfl_xor_sync(FULL, t, o);
        if (lane == 0) carry_s = t;
    }
    int x = val;
#pragma unroll
    for (int o = 1; o < 32; o <<= 1) {
        int t = __shfl_up_sync(FULL, x, o);
        if (lane >= o) x += t;
    }
    if (lane == 31) ws[w] = x;
    __syncthreads();
    if (w == 0) {
        int t = ws[lane];
        int y = t;
#pragma unroll
        for (int o = 1; o < 32; o <<= 1) {
            int u = __shfl_up_sync(FULL, y, o);
            if (lane >= o) y += u;
        }
        ws[lane] = y - t;
    }
    __syncthreads();
    int excl = x - val + ws[w] + carry_s;
    if (i < N) {
        g_rowoff[v][i] = excl;
        g_cursor[v][i] = excl;
        for (int k = raw; k < val; k++) g_csr[v][excl + k] = N;
        if (i == N - 1) g_rowoff[v][N] = excl + val;
    }
}

// ---------------- fill (CSR scatter of real edges) ----------------
__global__ void fill_kernel(const int* __restrict__ s0, const int* __restrict__ s1,
                            const int* __restrict__ s2,
                            const int* __restrict__ d0, const int* __restrict__ d1,
                            const int* __restrict__ d2, int E, int Q4) {
    int t = blockIdx.x * blockDim.x + threadIdx.x;
    if (t >= 3 * Q4) return;
    int v = t / Q4, q = t - v * Q4;
    const int* src = (v == 0) ? s0 : (v == 1) ? s1 : s2;
    const int* dst = (v == 0) ? d0 : (v == 1) ? d1 : d2;
    int base = q * 4;
    if (base + 4 <= E) {
        int4 ss = *(const int4*)&src[base];
        int4 dd = *(const int4*)&dst[base];
        g_csr[v][atomicAdd(&g_cursor[v][dd.x], 1)] = ss.x;
        g_csr[v][atomicAdd(&g_cursor[v][dd.y], 1)] = ss.y;
        g_csr[v][atomicAdd(&g_cursor[v][dd.z], 1)] = ss.z;
        g_csr[v][atomicAdd(&g_cursor[v][dd.w], 1)] = ss.w;
    } else {
        for (int e = base; e < E; e++)
            g_csr[v][atomicAdd(&g_cursor[v][dst[e]], 1)] = src[e];
    }
}

// ---------------- attention + fused reductions: 8-edge main + unpredicated 4-edge tail ----------------
__global__ __launch_bounds__(256) void attn_kernel(const float* __restrict__ Wq,
                                                   const float* __restrict__ bq,
                                                   const float* __restrict__ Wk,
                                                   const float* __restrict__ bk,
                                                   const float* __restrict__ Wm,
                                                   const float* __restrict__ b0,
                                                   const float* __restrict__ b1,
                                                   const float* __restrict__ b2,
                                                   int N, int totalWarps) {
    __shared__ float sWqP[2048];
    __shared__ float sWkP[2048];
    __shared__ float sqk[3], sdm[3];
    int tid = threadIdx.x;
    for (int i = tid; i < 2048; i += 256) {
        int h = i >> 7, j = i & 127;
        int u = (h >> 1) * 128 + (j & 3) * 32 + (j >> 2);
        sWqP[u * 2 + (h & 1)] = Wq[i];
        sWkP[u * 2 + (h & 1)] = Wk[i];
    }
    if (tid < 3) { sqk[tid] = 0.f; sdm[tid] = 0.f; }
    __syncthreads();
    const unsigned long long* q8 = (const unsigned long long*)sWqP;
    const unsigned long long* k8 = (const unsigned long long*)sWkP;
    int l = tid & 31;
    int h1 = l & 7;
    int h2 = l >> 2;
    float bqv = bq[l & 15], bkv = bk[l & 15];
    int gw = (blockIdx.x * 256 + tid) >> 5;

    for (int idx = gw; idx < 3 * N; idx += totalWarps) {
        int v = idx / N;
        int d = idx - v * N;
        int off = g_rowoff[v][d];
        int nE = g_rowoff[v][d + 1] - off;    // multiple of 4
        const int* csr = &g_csr[v][off];
        const float* elv = g_el[v];
        const __half* featv = g_feat[v];
        const float* bvp = (v == 0) ? b0 : (v == 1) ? b1 : b2;
        float er1 = g_er[v][d * 8 + h1];

        float acc0 = 0.f, acc1 = 0.f, acc2 = 0.f, acc3 = 0.f, ssum = 0.f;
        int base = 0;
        for (; base + 8 <= nE; base += 8) {
            int j0 = base + (l >> 3);
            int s0 = csr[j0];
            int s1 = csr[j0 + 4];
            float e0 = elv[s0 * 8 + h1] + er1;
            float e1 = elv[s1 * 8 + h1] + er1;
            float p0 = __expf(fmaxf(e0, 0.2f * e0));
            float p1 = __expf(fmaxf(e1, 0.2f * e1));
            ssum += p0 + p1;
            int sk[8];
#pragma unroll
            for (int k = 0; k < 4; k++) {
                sk[k] = __shfl_sync(FULL, s0, k * 8);
                sk[4 + k] = __shfl_sync(FULL, s1, k * 8);
            }
            uint2 f[8];
#pragma unroll
            for (int k = 0; k < 8; k++)
                f[k] = *(const uint2*)&featv[(size_t)sk[k] * 128 + l * 4];
#pragma unroll
            for (int k = 0; k < 8; k++) {
                float ak = __shfl_sync(FULL, (k < 4) ? p0 : p1, (k & 3) * 8 + h2);
                float2 a = __half22float2(*(__half2*)&f[k].x);
                float2 b2v = __half22float2(*(__half2*)&f[k].y);
                acc0 += ak * a.x;
                acc1 += ak * a.y;
                acc2 += ak * b2v.x;
                acc3 += ak * b2v.y;
            }
        }
        if (base < nE) {   // exactly 4 remaining (nE is a multiple of 4)
            int s0 = csr[base + (l >> 3)];
            float e0 = elv[s0 * 8 + h1] + er1;
            float p0 = __expf(fmaxf(e0, 0.2f * e0));
            ssum += p0;
            int sk[4];
#pragma unroll
            for (int k = 0; k < 4; k++) sk[k] = __shfl_sync(FULL, s0, k * 8);
            uint2 f[4];
#pragma unroll
            for (int k = 0; k < 4; k++)
                f[k] = *(const uint2*)&featv[(size_t)sk[k] * 128 + l * 4];
#pragma unroll
            for (int k = 0; k < 4; k++) {
                float ak = __shfl_sync(FULL, p0, k * 8 + h2);
                float2 a = __half22float2(*(__half2*)&f[k].x);
                float2 b2v = __half22float2(*(__half2*)&f[k].y);
                acc0 += ak * a.x;
                acc1 += ak * a.y;
                acc2 += ak * b2v.x;
                acc3 += ak * b2v.y;
            }
        }
        ssum += __shfl_xor_sync(FULL, ssum, 8);
        ssum += __shfl_xor_sync(FULL, ssum, 16);
        float sinv = 1.0f / __shfl_sync(FULL, ssum, h2);
        float4 bb = *(const float4*)&bvp[l * 4];
        float4 o;
        o.x = fmaxf(acc0 * sinv + bb.x, 0.f);
        o.y = fmaxf(acc1 * sinv + bb.y, 0.f);
        o.z = fmaxf(acc2 * sinv + bb.z, 0.f);
        o.w = fmaxf(acc3 * sinv + bb.w, 0.f);
        *(float4*)&g_views[(size_t)v * VSTRIDE + (size_t)d * 128 + l * 4] = o;

        // ---- fused reductions (parallel q/k accumulators, R15 form) ----
        float4 wm = *(const float4*)&Wm[(size_t)d * 128 + l * 4];
        float dm = o.x * wm.x + o.y * wm.y + o.z * wm.z + o.w * wm.w;
        dm = wsum(dm);

        unsigned long long vp[4];
        vp[0] = pk2(o.x, o.x); vp[1] = pk2(o.y, o.y);
        vp[2] = pk2(o.z, o.z); vp[3] = pk2(o.w, o.w);
        unsigned long long aq[8], ak8[8];
#pragma unroll
        for (int p = 0; p < 8; p++) { aq[p] = 0ull; ak8[p] = 0ull; }
#pragma unroll
        for (int p = 0; p < 8; p++)
#pragma unroll
            for (int jj = 0; jj < 4; jj++) {
                fma2(aq[p], vp[jj], q8[p * 128 + jj * 32 + l]);
                fma2(ak8[p], vp[jj], k8[p * 128 + jj * 32 + l]);
            }
        float c[32];
#pragma unroll
        for (int p = 0; p < 8; p++) {
            up2(aq[p], c[2 * p], c[2 * p + 1]);
            up2(ak8[p], c[16 + 2 * p], c[16 + 2 * p + 1]);
        }
#pragma unroll
        for (int s = 16; s >= 1; s >>= 1) {
            bool hi = (l & s) != 0;
#pragma unroll
            for (int j = 0; j < s; j++) {
                float give = hi ? c[j] : c[j + s];
                float get = __shfl_xor_sync(FULL, give, s);
                c[j] = (hi ? c[j + s] : c[j]) + get;
            }
        }
        float other = __shfl_xor_sync(FULL, c[0], 16);
        float q = (l < 16) ? c[0] : other;
        float k = (l < 16) ? other : c[0];
        float qk = wsum((q + bqv) * (k + bkv)) * 0.5f;
        if (l == 0) {
            atomicAdd(&sqk[v], qk);
            atomicAdd(&sdm[v], dm);
        }
    }
    __syncthreads();
    if (tid < 3) {
        atomicAdd(&g_qk[tid], (double)sqk[tid]);
        atomicAdd(&g_dm[tid], (double)sdm[tid]);
    }
}

// ---------------- scalar fusion coefficients ----------------
__global__ void coef_kernel(const float* __restrict__ bm, int N) {
    if (threadIdx.x != 0 || blockIdx.x != 0) return;
    double inv = 1.0 / sqrt(16.0 * (double)N);
    double L[3] = {g_qk[0] * inv, g_qk[1] * inv, g_qk[2] * inv};
    double mx = fmax(L[0], fmax(L[1], L[2]));
    double e0 = exp(L[0] - mx), e1 = exp(L[1] - mx), e2 = exp(L[2] - mx);
    double se = e0 + e1 + e2;
    double wv[3] = {e0 / se, e1 / se, e2 / se};
#pragma unroll
    for (int v = 0; v < 3; v++) {
        double cv = 0.8 * wv[v] + 0.2;
        double om = 1.0 / (1.0 + exp(-(cv * g_dm[v] + (double)bm[0])));
        g_coef[v] = (float)(om * cv);
        g_coef[3 + v] = (float)(0.5 * cv);
    }
}

// ---------------- final elementwise (+ restore g_cnt/g_bsum for next call) ----------------
__global__ __launch_bounds__(256) void final_kernel(float* __restrict__ out, int N) {
    int gidx = blockIdx.x * 256 + threadIdx.x;
    if (gidx < 3 * NMAX) ((int*)g_cnt)[gidx] = 0;
    if (gidx < 192) g_bsum[gidx] = 0;
    size_t total = (size_t)N * 128;
    size_t i = (size_t)gidx * 4;
    if (i >= total) return;
    float a0 = g_coef[0], a1 = g_coef[1], a2 = g_coef[2];
    float r0 = g_coef[3], r1 = g_coef[4], r2 = g_coef[5];
    float4 s = *(const float4*)&g_views[i];
    float4 t = *(const float4*)&g_views[VSTRIDE + i];
    float4 p = *(const float4*)&g_views[2 * VSTRIDE + i];
    float4 mv;
    mv.x = a0 * s.x + a1 * t.x + a2 * p.x;
    mv.y = a0 * s.y + a1 * t.y + a2 * p.y;
    mv.z = a0 * s.z + a1 * t.z + a2 * p.z;
    mv.w = a0 * s.w + a1 * t.w + a2 * p.w;
    *(float4*)&out[i] = mv;
    float4 o;
    o.x = r0 * s.x + 0.5f * mv.x; o.y = r0 * s.y + 0.5f * mv.y;
    o.z = r0 * s.z + 0.5f * mv.z; o.w = r0 * s.w + 0.5f * mv.w;
    *(float4*)&out[total + i] = o;
    o.x = r1 * t.x + 0.5f * mv.x; o.y = r1 * t.y + 0.5f * mv.y;
    o.z = r1 * t.z + 0.5f * mv.z; o.w = r1 * t.w + 0.5f * mv.w;
    *(float4*)&out[2 * total + i] = o;
    o.x = r2 * p.x + 0.5f * mv.x; o.y = r2 * p.y + 0.5f * mv.y;
    o.z = r2 * p.z + 0.5f * mv.z; o.w = r2 * p.w + 0.5f * mv.w;
    *(float4*)&out[3 * total + i] = o;
}

// ---------------- launch ----------------
extern "C" void kernel_launch(void* const* d_in, const int* in_sizes, int n_in,
                              void* d_out, int out_size) {
    const float* x = (const float*)d_in[0];
    const int* s0 = (const int*)d_in[1], *d0 = (const int*)d_in[2];
    const int* s1 = (const int*)d_in[3], *d1 = (const int*)d_in[4];
    const int* s2 = (const int*)d_in[5], *d2 = (const int*)d_in[6];
    const float* W0 = (const float*)d_in[7],  *al0 = (const float*)d_in[8],
               * ar0 = (const float*)d_in[9],  *b0 = (const float*)d_in[10];
    const float* W1 = (const float*)d_in[11], *al1 = (const float*)d_in[12],
               * ar1 = (const float*)d_in[13], *b1 = (const float*)d_in[14];
    const float* W2 = (const float*)d_in[15], *al2 = (const float*)d_in[16],
               * ar2 = (const float*)d_in[17], *b2 = (const float*)d_in[18];
    const float* Wq = (const float*)d_in[19];
    const float* bq = (const float*)d_in[20];
    const float* Wk = (const float*)d_in[21];
    const float* bk = (const float*)d_in[22];
    const float* Wm = (const float*)d_in[23];
    const float* bm = (const float*)d_in[24];
    float* out = (float*)d_out;

    int N = in_sizes[0] / 128;
    int E = in_sizes[1];
    int BV = (N + 1023) >> 10;
    int NT = (N + 127) >> 7;
    int Q4 = (E + 3) >> 2;
    int gemmBlocks = NT;
    int edgeBlocks = (3 * Q4 + 255) / 256;
    int attnBlocks = 1184;

    static int smem_set = 0;
    if (!smem_set) {
        cudaFuncSetAttribute(fat1_kernel, cudaFuncAttributeMaxDynamicSharedMemorySize, DS_TOTAL);
        smem_set = 1;
    }

    fat1_kernel<<<gemmBlocks + edgeBlocks, 256, DS_TOTAL>>>(x, W0, W1, W2,
                                                            al0, al1, al2, ar0, ar1, ar2,
                                                            d0, d1, d2,
                                                            N, E, gemmBlocks, edgeBlocks, Q4);
    scanDL_kernel<<<3 * BV, 1024>>>(N, BV, E);
    fill_kernel<<<edgeBlocks, 256>>>(s0, s1, s2, d0, d1, d2, E, Q4);
    attn_kernel<<<attnBlocks, 256>>>(Wq, bq, Wk, bk, Wm, b0, b1, b2, N, attnBlocks * 8);
    coef_kernel<<<1, 32>>>(bm, N);
    final_kernel<<<((N * 32) + 255) / 256, 256>>>(out, N);
}